// round 1
// baseline (speedup 1.0000x reference)
#include <cuda_runtime.h>
#include <math.h>

// Problem constants
#define BDIM 4
#define CDIM 256
#define LDIM 32768
#define CHUNK 512
#define NCHUNK 64   // LDIM / CHUNK
#define KT 16

// ---------------------------------------------------------------------------
// Scratch (static device arrays — no allocation allowed in kernel_launch)
// ---------------------------------------------------------------------------
__device__ float gP[BDIM * NCHUNK * 3 * 128 * 128];  // partial Gram tiles (~50 MB)
__device__ float gG[BDIM * CDIM * CDIM];             // G = x x^T per batch
__device__ float gH2[BDIM * CDIM * CDIM];            // H2 = W_K * G
__device__ float gAm[BDIM * CDIM * CDIM];            // logits -> softmax in place
__device__ float gM[BDIM * CDIM * CDIM];             // M = A * W_V
__device__ float gWVT[CDIM * CDIM];                  // W_V transposed

// ---------------------------------------------------------------------------
// f32x2 packed-FMA SGEMM core (NT: C[i,j] = sum_k A[i,k] * B[j,k])
// 128x128 block tile, 256 threads, 8x8 per-thread tile held as f32x2 pairs.
// A is stored in smem pre-duplicated into (a,a) 64-bit pairs so the inner
// loop needs no packing: 32 fma.rn.f32x2 + 6 LDS.128 per k-step per thread.
// ---------------------------------------------------------------------------
struct __align__(16) SmemNT {
    unsigned long long As2[KT][130];  // duplicated pairs, row stride 130 (16B-aligned, reduces store conflicts)
    float Bs[KT][132];                // row stride 132 (16B-aligned)
};

__device__ __forceinline__ unsigned long long pack2(float v) {
    unsigned long long r;
    asm("mov.b64 %0, {%1, %1};" : "=l"(r) : "f"(v));
    return r;
}

__device__ __forceinline__ void fma2(unsigned long long& acc,
                                     unsigned long long a,
                                     unsigned long long b) {
    asm("fma.rn.f32x2 %0, %1, %2, %0;" : "+l"(acc) : "l"(a), "l"(b));
}

__device__ __forceinline__ void compute_tile(const SmemNT& s, int tx, int ty,
                                             unsigned long long acc[8][4]) {
#pragma unroll
    for (int kk = 0; kk < KT; kk++) {
        unsigned long long a2[8], b2[4];
        const ulonglong2* ap = (const ulonglong2*)&s.As2[kk][ty * 8];
        ulonglong2 t0 = ap[0], t1 = ap[1], t2 = ap[2], t3 = ap[3];
        a2[0] = t0.x; a2[1] = t0.y; a2[2] = t1.x; a2[3] = t1.y;
        a2[4] = t2.x; a2[5] = t2.y; a2[6] = t3.x; a2[7] = t3.y;
        const ulonglong2* bp = (const ulonglong2*)&s.Bs[kk][tx * 8];
        ulonglong2 u0 = bp[0], u1 = bp[1];
        b2[0] = u0.x; b2[1] = u0.y; b2[2] = u1.x; b2[3] = u1.y;
#pragma unroll
        for (int i = 0; i < 8; i++)
#pragma unroll
            for (int j = 0; j < 4; j++) fma2(acc[i][j], a2[i], b2[j]);
    }
}

// NT GEMM: both operands row-major with contraction dim contiguous.
__device__ __forceinline__ void gemm_nt_128(SmemNT& s,
                                            const float* __restrict__ A, int lda,
                                            const float* __restrict__ B, int ldb,
                                            float* __restrict__ Cc, int ldc,
                                            int nkt) {
    const int tid = threadIdx.x;
    const int tx = tid & 15, ty = tid >> 4;
    const int r0 = tid >> 2;              // 0..63 (plus +64 twin row)
    const int kq = (tid & 3) * 4;         // k quad offset 0/4/8/12

    unsigned long long acc[8][4];
#pragma unroll
    for (int i = 0; i < 8; i++)
#pragma unroll
        for (int j = 0; j < 4; j++) acc[i][j] = 0ull;

    float4 pa0 = *(const float4*)(A + (size_t)r0 * lda + kq);
    float4 pa1 = *(const float4*)(A + (size_t)(r0 + 64) * lda + kq);
    float4 pb0 = *(const float4*)(B + (size_t)r0 * ldb + kq);
    float4 pb1 = *(const float4*)(B + (size_t)(r0 + 64) * ldb + kq);

    for (int kt = 0; kt < nkt; kt++) {
#pragma unroll
        for (int j = 0; j < 4; j++) {
            s.As2[kq + j][r0]      = pack2(((const float*)&pa0)[j]);
            s.As2[kq + j][r0 + 64] = pack2(((const float*)&pa1)[j]);
            s.Bs[kq + j][r0]       = ((const float*)&pb0)[j];
            s.Bs[kq + j][r0 + 64]  = ((const float*)&pb1)[j];
        }
        __syncthreads();
        if (kt + 1 < nkt) {
            const float* An = A + (size_t)(kt + 1) * KT;
            const float* Bn = B + (size_t)(kt + 1) * KT;
            pa0 = *(const float4*)(An + (size_t)r0 * lda + kq);
            pa1 = *(const float4*)(An + (size_t)(r0 + 64) * lda + kq);
            pb0 = *(const float4*)(Bn + (size_t)r0 * ldb + kq);
            pb1 = *(const float4*)(Bn + (size_t)(r0 + 64) * ldb + kq);
        }
        compute_tile(s, tx, ty, acc);
        __syncthreads();
    }

#pragma unroll
    for (int i = 0; i < 8; i++) {
        float* cp = Cc + (size_t)(ty * 8 + i) * ldc + tx * 8;
        ulonglong2 v0; v0.x = acc[i][0]; v0.y = acc[i][1];
        ulonglong2 v1; v1.x = acc[i][2]; v1.y = acc[i][3];
        *(ulonglong2*)cp = v0;
        *(ulonglong2*)(cp + 4) = v1;
    }
}

// ---------------------------------------------------------------------------
// Phase 1: partial Gram tiles. G symmetric -> only tiles (0,0),(0,1),(1,1).
// grid (3, NCHUNK, BDIM)
// ---------------------------------------------------------------------------
__global__ void __launch_bounds__(256, 2) xxt_partial(const float* __restrict__ x) {
    __shared__ SmemNT s;
    const int t = blockIdx.x, chunk = blockIdx.y, b = blockIdx.z;
    const int ti = (t == 2) ? 1 : 0;
    const int tj = (t == 0) ? 0 : 1;
    const float* Ab = x + ((size_t)b * CDIM + ti * 128) * LDIM + (size_t)chunk * CHUNK;
    const float* Bb = x + ((size_t)b * CDIM + tj * 128) * LDIM + (size_t)chunk * CHUNK;
    float* Cb = gP + (((size_t)b * NCHUNK + chunk) * 3 + t) * 16384;
    gemm_nt_128(s, Ab, LDIM, Bb, LDIM, Cb, 128, CHUNK / KT);
}

// Phase 2: reduce partials into G, mirroring the off-diagonal tile.
// grid (64, 3, BDIM), 256 threads -> one G element each
__global__ void xxt_reduce() {
    const int e = blockIdx.x * 256 + threadIdx.x;  // 0..16383
    const int t = blockIdx.y, b = blockIdx.z;
    const int ii = e >> 7, jj = e & 127;
    const float* p = gP + ((size_t)b * NCHUNK * 3 + t) * 16384 + e;
    float sum = 0.f;
#pragma unroll 8
    for (int ch = 0; ch < NCHUNK; ch++) sum += p[(size_t)ch * 3 * 16384];
    const int bi = (t == 2) ? 128 : 0;
    const int bj = (t == 0) ? 0 : 128;
    gG[(size_t)b * 65536 + (size_t)(bi + ii) * 256 + (bj + jj)] = sum;
    if (t == 1)  // mirror upper-right tile into lower-left
        gG[(size_t)b * 65536 + (size_t)(128 + jj) * 256 + ii] = sum;
}

// One-time transpose of W_V so the M GEMM is also NT-form.
__global__ void transpose_wv(const float* __restrict__ wv) {
    const int c = blockIdx.x, k = threadIdx.x;
    gWVT[c * 256 + k] = wv[k * 256 + c];
}

// ---------------------------------------------------------------------------
// Middle 256^3 GEMMs (all NT thanks to G symmetry):
//   H2[b][k][c] = sum_c' W_K[k,c'] G[b][c,c']      (= (W_K G)[k,c])
//   A_[b][q][k] = sum_c  W_Q[q,c]  H2[b][k,c]
//   M [b][q][c] = sum_k  A[b][q,k] WVT[c,k]
// grid (2, 2, BDIM) each
// ---------------------------------------------------------------------------
__global__ void __launch_bounds__(256, 2) gemm_h2_kernel(const float* __restrict__ wk) {
    __shared__ SmemNT s;
    const int bx = blockIdx.x, by = blockIdx.y, b = blockIdx.z;
    gemm_nt_128(s, wk + (size_t)by * 128 * 256, 256,
                gG + (size_t)b * 65536 + (size_t)bx * 128 * 256, 256,
                gH2 + (size_t)b * 65536 + (size_t)by * 128 * 256 + bx * 128, 256, 16);
}

__global__ void __launch_bounds__(256, 2) gemm_attn_kernel(const float* __restrict__ wq) {
    __shared__ SmemNT s;
    const int bx = blockIdx.x, by = blockIdx.y, b = blockIdx.z;
    gemm_nt_128(s, wq + (size_t)by * 128 * 256, 256,
                gH2 + (size_t)b * 65536 + (size_t)bx * 128 * 256, 256,
                gAm + (size_t)b * 65536 + (size_t)by * 128 * 256 + bx * 128, 256, 16);
}

__global__ void __launch_bounds__(256, 2) gemm_m_kernel() {
    __shared__ SmemNT s;
    const int bx = blockIdx.x, by = blockIdx.y, b = blockIdx.z;
    gemm_nt_128(s, gAm + (size_t)b * 65536 + (size_t)by * 128 * 256, 256,
                gWVT + (size_t)bx * 128 * 256, 256,
                gM + (size_t)b * 65536 + (size_t)by * 128 * 256 + bx * 128, 256, 16);
}

// ---------------------------------------------------------------------------
// Softmax over q (axis=-2) for each (b, k) column, in place on gAm.
// grid (4, BDIM), 256 threads: 64 columns per block, 4 q-slices per column.
// ---------------------------------------------------------------------------
__global__ void softmax_kernel() {
    const int b = blockIdx.y;
    const int tc = threadIdx.x & 63, tq = threadIdx.x >> 6;  // tq in 0..3
    const int col = blockIdx.x * 64 + tc;
    float* Ab = gAm + (size_t)b * 65536;

    float v[64];
    float m = -3.0e38f;
#pragma unroll
    for (int qi = 0; qi < 64; qi++) {
        v[qi] = Ab[(size_t)(tq + qi * 4) * 256 + col];
        m = fmaxf(m, v[qi]);
    }
    __shared__ float red[4][64];
    red[tq][tc] = m;
    __syncthreads();
    const float mm = fmaxf(fmaxf(red[0][tc], red[1][tc]),
                           fmaxf(red[2][tc], red[3][tc]));
    __syncthreads();
    float ssum = 0.f;
#pragma unroll
    for (int qi = 0; qi < 64; qi++) {
        v[qi] = expf(v[qi] - mm);
        ssum += v[qi];
    }
    red[tq][tc] = ssum;
    __syncthreads();
    const float tot = red[0][tc] + red[1][tc] + red[2][tc] + red[3][tc];
    const float inv = 1.f / tot;
#pragma unroll
    for (int qi = 0; qi < 64; qi++)
        Ab[(size_t)(tq + qi * 4) * 256 + col] = v[qi] * inv;
}

// ---------------------------------------------------------------------------
// Phase 5: y[b] = M[b] @ x[b]   (NN form: B = x with output dim contiguous)
// grid (LDIM/128, 2, BDIM)
// ---------------------------------------------------------------------------
__global__ void __launch_bounds__(256, 2) final_nn_kernel(const float* __restrict__ x,
                                                          float* __restrict__ y) {
    __shared__ SmemNT s;
    const int tid = threadIdx.x;
    const int tx = tid & 15, ty = tid >> 4;
    const int r0 = tid >> 2, kq = (tid & 3) * 4;      // A-tile load mapping
    const int krow = tid >> 5, cq = (tid & 31) * 4;   // B-tile load mapping
    const int lx = blockIdx.x, qy = blockIdx.y, b = blockIdx.z;

    const float* Ab = gM + (size_t)b * 65536 + (size_t)qy * 128 * 256;
    const float* Bb = x + (size_t)b * CDIM * LDIM + (size_t)lx * 128;
    float* yb = y + ((size_t)b * CDIM + (size_t)qy * 128) * LDIM + (size_t)lx * 128;

    unsigned long long acc[8][4];
#pragma unroll
    for (int i = 0; i < 8; i++)
#pragma unroll
        for (int j = 0; j < 4; j++) acc[i][j] = 0ull;

    float4 pa0 = *(const float4*)(Ab + (size_t)r0 * 256 + kq);
    float4 pa1 = *(const float4*)(Ab + (size_t)(r0 + 64) * 256 + kq);
    float4 pb0 = *(const float4*)(Bb + (size_t)krow * LDIM + cq);
    float4 pb1 = *(const float4*)(Bb + (size_t)(krow + 8) * LDIM + cq);

    for (int kt = 0; kt < 16; kt++) {
#pragma unroll
        for (int j = 0; j < 4; j++) {
            s.As2[kq + j][r0]      = pack2(((const float*)&pa0)[j]);
            s.As2[kq + j][r0 + 64] = pack2(((const float*)&pa1)[j]);
        }
        *(float4*)&s.Bs[krow][cq]     = pb0;
        *(float4*)&s.Bs[krow + 8][cq] = pb1;
        __syncthreads();
        if (kt + 1 < 16) {
            const int k0 = (kt + 1) * KT;
            pa0 = *(const float4*)(Ab + (size_t)r0 * 256 + k0 + kq);
            pa1 = *(const float4*)(Ab + (size_t)(r0 + 64) * 256 + k0 + kq);
            pb0 = *(const float4*)(Bb + (size_t)(k0 + krow) * LDIM + cq);
            pb1 = *(const float4*)(Bb + (size_t)(k0 + krow + 8) * LDIM + cq);
        }
        compute_tile(s, tx, ty, acc);
        __syncthreads();
    }

#pragma unroll
    for (int i = 0; i < 8; i++) {
        float* cp = yb + (size_t)(ty * 8 + i) * LDIM + tx * 8;
        ulonglong2 v0; v0.x = acc[i][0]; v0.y = acc[i][1];
        ulonglong2 v1; v1.x = acc[i][2]; v1.y = acc[i][3];
        *(ulonglong2*)cp = v0;
        *(ulonglong2*)(cp + 4) = v1;
    }
}

// ---------------------------------------------------------------------------
// Launch
// ---------------------------------------------------------------------------
extern "C" void kernel_launch(void* const* d_in, const int* in_sizes, int n_in,
                              void* d_out, int out_size) {
    const float *x = nullptr, *wq = nullptr, *wk = nullptr, *wv = nullptr;
    for (int i = 0; i < n_in; i++) {
        if (in_sizes[i] == BDIM * CDIM * LDIM) {
            x = (const float*)d_in[i];
        } else if (!wq) wq = (const float*)d_in[i];
        else if (!wk) wk = (const float*)d_in[i];
        else wv = (const float*)d_in[i];
    }
    float* y = (float*)d_out;

    xxt_partial<<<dim3(3, NCHUNK, BDIM), 256>>>(x);
    xxt_reduce<<<dim3(64, 3, BDIM), 256>>>();
    transpose_wv<<<256, 256>>>(wv);
    gemm_h2_kernel<<<dim3(2, 2, BDIM), 256>>>(wk);
    gemm_attn_kernel<<<dim3(2, 2, BDIM), 256>>>(wq);
    softmax_kernel<<<dim3(4, BDIM), 256>>>();
    gemm_m_kernel<<<dim3(2, 2, BDIM), 256>>>();
    final_nn_kernel<<<dim3(LDIM / 128, 2, BDIM), 256>>>(x, y);
}

// round 2
// speedup vs baseline: 1.0041x; 1.0041x over previous
#include <cuda_runtime.h>
#include <math.h>

// Problem constants
#define BDIM 4
#define CDIM 256
#define LDIM 32768
#define CHUNK 512
#define NCHUNK 64   // LDIM / CHUNK
#define KT 16

// ---------------------------------------------------------------------------
// Scratch (static device arrays — no allocation allowed in kernel_launch)
// ---------------------------------------------------------------------------
__device__ float gP[BDIM * NCHUNK * 3 * 128 * 128];  // partial Gram tiles (~50 MB)
__device__ float gG[BDIM * CDIM * CDIM];             // G = x x^T per batch
__device__ float gH2[BDIM * CDIM * CDIM];            // H2 = W_K * G
__device__ float gAm[BDIM * CDIM * CDIM];            // logits -> softmax in place
__device__ float gM[BDIM * CDIM * CDIM];             // M = A * W_V
__device__ float gWVT[CDIM * CDIM];                  // W_V transposed

// ---------------------------------------------------------------------------
// f32x2 packed-FMA SGEMM core (NT: C[i,j] = sum_k A[i,k] * B[j,k])
// 128x128 block tile, 256 threads, 8x8 per-thread tile held as f32x2 pairs.
// A is stored in smem pre-duplicated into (a,a) 64-bit pairs so the inner
// loop needs no packing: 32 fma.rn.f32x2 + 6 LDS.128 per k-step per thread.
// ---------------------------------------------------------------------------
struct __align__(16) SmemNT {
    unsigned long long As2[KT][130];  // duplicated pairs, row stride 130 (16B-aligned, reduces store conflicts)
    float Bs[KT][132];                // row stride 132 (16B-aligned)
};

__device__ __forceinline__ unsigned long long pack2(float v) {
    unsigned long long r;
    asm("mov.b64 %0, {%1, %1};" : "=l"(r) : "f"(v));
    return r;
}

__device__ __forceinline__ void fma2(unsigned long long& acc,
                                     unsigned long long a,
                                     unsigned long long b) {
    asm("fma.rn.f32x2 %0, %1, %2, %0;" : "+l"(acc) : "l"(a), "l"(b));
}

__device__ __forceinline__ void compute_tile(const SmemNT& s, int tx, int ty,
                                             unsigned long long acc[8][4]) {
#pragma unroll
    for (int kk = 0; kk < KT; kk++) {
        unsigned long long a2[8], b2[4];
        const ulonglong2* ap = (const ulonglong2*)&s.As2[kk][ty * 8];
        ulonglong2 t0 = ap[0], t1 = ap[1], t2 = ap[2], t3 = ap[3];
        a2[0] = t0.x; a2[1] = t0.y; a2[2] = t1.x; a2[3] = t1.y;
        a2[4] = t2.x; a2[5] = t2.y; a2[6] = t3.x; a2[7] = t3.y;
        const ulonglong2* bp = (const ulonglong2*)&s.Bs[kk][tx * 8];
        ulonglong2 u0 = bp[0], u1 = bp[1];
        b2[0] = u0.x; b2[1] = u0.y; b2[2] = u1.x; b2[3] = u1.y;
#pragma unroll
        for (int i = 0; i < 8; i++)
#pragma unroll
            for (int j = 0; j < 4; j++) fma2(acc[i][j], a2[i], b2[j]);
    }
}

// NT GEMM: both operands row-major with contraction dim contiguous.
__device__ __forceinline__ void gemm_nt_128(SmemNT& s,
                                            const float* __restrict__ A, int lda,
                                            const float* __restrict__ B, int ldb,
                                            float* __restrict__ Cc, int ldc,
                                            int nkt) {
    const int tid = threadIdx.x;
    const int tx = tid & 15, ty = tid >> 4;
    const int r0 = tid >> 2;              // 0..63 (plus +64 twin row)
    const int kq = (tid & 3) * 4;         // k quad offset 0/4/8/12

    unsigned long long acc[8][4];
#pragma unroll
    for (int i = 0; i < 8; i++)
#pragma unroll
        for (int j = 0; j < 4; j++) acc[i][j] = 0ull;

    float4 pa0 = *(const float4*)(A + (size_t)r0 * lda + kq);
    float4 pa1 = *(const float4*)(A + (size_t)(r0 + 64) * lda + kq);
    float4 pb0 = *(const float4*)(B + (size_t)r0 * ldb + kq);
    float4 pb1 = *(const float4*)(B + (size_t)(r0 + 64) * ldb + kq);

    for (int kt = 0; kt < nkt; kt++) {
#pragma unroll
        for (int j = 0; j < 4; j++) {
            s.As2[kq + j][r0]      = pack2(((const float*)&pa0)[j]);
            s.As2[kq + j][r0 + 64] = pack2(((const float*)&pa1)[j]);
            s.Bs[kq + j][r0]       = ((const float*)&pb0)[j];
            s.Bs[kq + j][r0 + 64]  = ((const float*)&pb1)[j];
        }
        __syncthreads();
        if (kt + 1 < nkt) {
            const float* An = A + (size_t)(kt + 1) * KT;
            const float* Bn = B + (size_t)(kt + 1) * KT;
            pa0 = *(const float4*)(An + (size_t)r0 * lda + kq);
            pa1 = *(const float4*)(An + (size_t)(r0 + 64) * lda + kq);
            pb0 = *(const float4*)(Bn + (size_t)r0 * ldb + kq);
            pb1 = *(const float4*)(Bn + (size_t)(r0 + 64) * ldb + kq);
        }
        compute_tile(s, tx, ty, acc);
        __syncthreads();
    }

#pragma unroll
    for (int i = 0; i < 8; i++) {
        float* cp = Cc + (size_t)(ty * 8 + i) * ldc + tx * 8;
        ulonglong2 v0; v0.x = acc[i][0]; v0.y = acc[i][1];
        ulonglong2 v1; v1.x = acc[i][2]; v1.y = acc[i][3];
        *(ulonglong2*)cp = v0;
        *(ulonglong2*)(cp + 4) = v1;
    }
}

// ---------------------------------------------------------------------------
// Phase 1: partial Gram tiles. G symmetric -> only tiles (0,0),(0,1),(1,1).
// grid (3, NCHUNK, BDIM)
// ---------------------------------------------------------------------------
__global__ void __launch_bounds__(256, 2) xxt_partial(const float* __restrict__ x) {
    __shared__ SmemNT s;
    const int t = blockIdx.x, chunk = blockIdx.y, b = blockIdx.z;
    const int ti = (t == 2) ? 1 : 0;
    const int tj = (t == 0) ? 0 : 1;
    const float* Ab = x + ((size_t)b * CDIM + ti * 128) * LDIM + (size_t)chunk * CHUNK;
    const float* Bb = x + ((size_t)b * CDIM + tj * 128) * LDIM + (size_t)chunk * CHUNK;
    float* Cb = gP + (((size_t)b * NCHUNK + chunk) * 3 + t) * 16384;
    gemm_nt_128(s, Ab, LDIM, Bb, LDIM, Cb, 128, CHUNK / KT);
}

// Phase 2: reduce partials into G, mirroring the off-diagonal tile.
// grid (64, 3, BDIM), 256 threads -> one G element each
__global__ void xxt_reduce() {
    const int e = blockIdx.x * 256 + threadIdx.x;  // 0..16383
    const int t = blockIdx.y, b = blockIdx.z;
    const int ii = e >> 7, jj = e & 127;
    const float* p = gP + ((size_t)b * NCHUNK * 3 + t) * 16384 + e;
    float sum = 0.f;
#pragma unroll 8
    for (int ch = 0; ch < NCHUNK; ch++) sum += p[(size_t)ch * 3 * 16384];
    const int bi = (t == 2) ? 128 : 0;
    const int bj = (t == 0) ? 0 : 128;
    gG[(size_t)b * 65536 + (size_t)(bi + ii) * 256 + (bj + jj)] = sum;
    if (t == 1)  // mirror upper-right tile into lower-left
        gG[(size_t)b * 65536 + (size_t)(128 + jj) * 256 + ii] = sum;
}

// One-time transpose of W_V so the M GEMM is also NT-form.
__global__ void transpose_wv(const float* __restrict__ wv) {
    const int c = blockIdx.x, k = threadIdx.x;
    gWVT[c * 256 + k] = wv[k * 256 + c];
}

// ---------------------------------------------------------------------------
// Middle 256^3 GEMMs (all NT thanks to G symmetry):
//   H2[b][k][c] = sum_c' W_K[k,c'] G[b][c,c']      (= (W_K G)[k,c])
//   A_[b][q][k] = sum_c  W_Q[q,c]  H2[b][k,c]
//   M [b][q][c] = sum_k  A[b][q,k] WVT[c,k]
// grid (2, 2, BDIM) each
// ---------------------------------------------------------------------------
__global__ void __launch_bounds__(256, 2) gemm_h2_kernel(const float* __restrict__ wk) {
    __shared__ SmemNT s;
    const int bx = blockIdx.x, by = blockIdx.y, b = blockIdx.z;
    gemm_nt_128(s, wk + (size_t)by * 128 * 256, 256,
                gG + (size_t)b * 65536 + (size_t)bx * 128 * 256, 256,
                gH2 + (size_t)b * 65536 + (size_t)by * 128 * 256 + bx * 128, 256, 16);
}

__global__ void __launch_bounds__(256, 2) gemm_attn_kernel(const float* __restrict__ wq) {
    __shared__ SmemNT s;
    const int bx = blockIdx.x, by = blockIdx.y, b = blockIdx.z;
    gemm_nt_128(s, wq + (size_t)by * 128 * 256, 256,
                gH2 + (size_t)b * 65536 + (size_t)bx * 128 * 256, 256,
                gAm + (size_t)b * 65536 + (size_t)by * 128 * 256 + bx * 128, 256, 16);
}

__global__ void __launch_bounds__(256, 2) gemm_m_kernel() {
    __shared__ SmemNT s;
    const int bx = blockIdx.x, by = blockIdx.y, b = blockIdx.z;
    gemm_nt_128(s, gAm + (size_t)b * 65536 + (size_t)by * 128 * 256, 256,
                gWVT + (size_t)bx * 128 * 256, 256,
                gM + (size_t)b * 65536 + (size_t)by * 128 * 256 + bx * 128, 256, 16);
}

// ---------------------------------------------------------------------------
// Softmax over q (axis=-2) for each (b, k) column, in place on gAm.
// grid (4, BDIM), 256 threads: 64 columns per block, 4 q-slices per column.
// ---------------------------------------------------------------------------
__global__ void softmax_kernel() {
    const int b = blockIdx.y;
    const int tc = threadIdx.x & 63, tq = threadIdx.x >> 6;  // tq in 0..3
    const int col = blockIdx.x * 64 + tc;
    float* Ab = gAm + (size_t)b * 65536;

    float v[64];
    float m = -3.0e38f;
#pragma unroll
    for (int qi = 0; qi < 64; qi++) {
        v[qi] = Ab[(size_t)(tq + qi * 4) * 256 + col];
        m = fmaxf(m, v[qi]);
    }
    __shared__ float red[4][64];
    red[tq][tc] = m;
    __syncthreads();
    const float mm = fmaxf(fmaxf(red[0][tc], red[1][tc]),
                           fmaxf(red[2][tc], red[3][tc]));
    __syncthreads();
    float ssum = 0.f;
#pragma unroll
    for (int qi = 0; qi < 64; qi++) {
        v[qi] = expf(v[qi] - mm);
        ssum += v[qi];
    }
    red[tq][tc] = ssum;
    __syncthreads();
    const float tot = red[0][tc] + red[1][tc] + red[2][tc] + red[3][tc];
    const float inv = 1.f / tot;
#pragma unroll
    for (int qi = 0; qi < 64; qi++)
        Ab[(size_t)(tq + qi * 4) * 256 + col] = v[qi] * inv;
}

// ---------------------------------------------------------------------------
// Phase 5: y[b] = M[b] @ x[b]   (NN form: B = x with output dim contiguous)
// grid (LDIM/128, 2, BDIM)
// ---------------------------------------------------------------------------
__global__ void __launch_bounds__(256, 2) final_nn_kernel(const float* __restrict__ x,
                                                          float* __restrict__ y) {
    __shared__ SmemNT s;
    const int tid = threadIdx.x;
    const int tx = tid & 15, ty = tid >> 4;
    const int r0 = tid >> 2, kq = (tid & 3) * 4;      // A-tile load mapping
    const int krow = tid >> 5, cq = (tid & 31) * 4;   // B-tile load mapping
    const int lx = blockIdx.x, qy = blockIdx.y, b = blockIdx.z;

    const float* Ab = gM + (size_t)b * 65536 + (size_t)qy * 128 * 256;
    const float* Bb = x + (size_t)b * CDIM * LDIM + (size_t)lx * 128;
    float* yb = y + ((size_t)b * CDIM + (size_t)qy * 128) * LDIM + (size_t)lx * 128;

    unsigned long long acc[8][4];
#pragma unroll
    for (int i = 0; i < 8; i++)
#pragma unroll
        for (int j = 0; j < 4; j++) acc[i][j] = 0ull;

    float4 pa0 = *(const float4*)(Ab + (size_t)r0 * 256 + kq);
    float4 pa1 = *(const float4*)(Ab + (size_t)(r0 + 64) * 256 + kq);
    float4 pb0 = *(const float4*)(Bb + (size_t)krow * LDIM + cq);
    float4 pb1 = *(const float4*)(Bb + (size_t)(krow + 8) * LDIM + cq);

    for (int kt = 0; kt < 16; kt++) {
#pragma unroll
        for (int j = 0; j < 4; j++) {
            s.As2[kq + j][r0]      = pack2(((const float*)&pa0)[j]);
            s.As2[kq + j][r0 + 64] = pack2(((const float*)&pa1)[j]);
        }
        *(float4*)&s.Bs[krow][cq]     = pb0;
        *(float4*)&s.Bs[krow + 8][cq] = pb1;
        __syncthreads();
        if (kt + 1 < 16) {
            const int k0 = (kt + 1) * KT;
            pa0 = *(const float4*)(Ab + (size_t)r0 * 256 + k0 + kq);
            pa1 = *(const float4*)(Ab + (size_t)(r0 + 64) * 256 + k0 + kq);
            pb0 = *(const float4*)(Bb + (size_t)(k0 + krow) * LDIM + cq);
            pb1 = *(const float4*)(Bb + (size_t)(k0 + krow + 8) * LDIM + cq);
        }
        compute_tile(s, tx, ty, acc);
        __syncthreads();
    }

#pragma unroll
    for (int i = 0; i < 8; i++) {
        float* cp = yb + (size_t)(ty * 8 + i) * LDIM + tx * 8;
        ulonglong2 v0; v0.x = acc[i][0]; v0.y = acc[i][1];
        ulonglong2 v1; v1.x = acc[i][2]; v1.y = acc[i][3];
        *(ulonglong2*)cp = v0;
        *(ulonglong2*)(cp + 4) = v1;
    }
}

// ---------------------------------------------------------------------------
// Launch
// ---------------------------------------------------------------------------
extern "C" void kernel_launch(void* const* d_in, const int* in_sizes, int n_in,
                              void* d_out, int out_size) {
    const float *x = nullptr, *wq = nullptr, *wk = nullptr, *wv = nullptr;
    for (int i = 0; i < n_in; i++) {
        if (in_sizes[i] == BDIM * CDIM * LDIM) {
            x = (const float*)d_in[i];
        } else if (!wq) wq = (const float*)d_in[i];
        else if (!wk) wk = (const float*)d_in[i];
        else wv = (const float*)d_in[i];
    }
    float* y = (float*)d_out;

    xxt_partial<<<dim3(3, NCHUNK, BDIM), 256>>>(x);
    xxt_reduce<<<dim3(64, 3, BDIM), 256>>>();
    transpose_wv<<<256, 256>>>(wv);
    gemm_h2_kernel<<<dim3(2, 2, BDIM), 256>>>(wk);
    gemm_attn_kernel<<<dim3(2, 2, BDIM), 256>>>(wq);
    softmax_kernel<<<dim3(4, BDIM), 256>>>();
    gemm_m_kernel<<<dim3(2, 2, BDIM), 256>>>();
    final_nn_kernel<<<dim3(LDIM / 128, 2, BDIM), 256>>>(x, y);
}

// round 4
// speedup vs baseline: 1.3077x; 1.3024x over previous
#include <cuda_runtime.h>
#include <cstdint>
#include <math.h>

// Problem constants
#define BDIM 4
#define CDIM 256
#define LDIM 32768

// Gram split-K
#define NSPLIT 32
#define KCTA   (LDIM / NSPLIT)   // 1024
#define NKT_GRAM (KCTA / 16)     // 64 k-steps of 16

// ---------------------------------------------------------------------------
// Scratch (static device arrays)
// ---------------------------------------------------------------------------
__device__ float gP[BDIM * NSPLIT * 3 * 128 * 128];  // partial Gram tiles (25MB)
__device__ float gG[BDIM * CDIM * CDIM];             // G = x x^T
__device__ float gH2[BDIM * CDIM * CDIM];            // H2 = W_K * G
__device__ float gAm[BDIM * CDIM * CDIM];            // logits -> softmax
__device__ float gM[BDIM * CDIM * CDIM];             // M = A * W_V
__device__ float gWVT[CDIM * CDIM];                  // W_V transposed

// ---------------------------------------------------------------------------
// mma.sync tf32 (sm_80+ PTX — works under compute_100)
// ---------------------------------------------------------------------------
__device__ __forceinline__ float tf32_hi(float v) {
    uint32_t u;
    asm("cvt.rna.tf32.f32 %0, %1;" : "=r"(u) : "f"(v));
    return __uint_as_float(u);
}

#define MMA_TF32(c, a, b)                                                     \
    asm volatile("mma.sync.aligned.m16n8k8.row.col.f32.tf32.tf32.f32 "        \
                 "{%0,%1,%2,%3}, {%4,%5,%6,%7}, {%8,%9}, {%0,%1,%2,%3};"      \
                 : "+f"((c)[0]), "+f"((c)[1]), "+f"((c)[2]), "+f"((c)[3])     \
                 : "r"((a)[0]), "r"((a)[1]), "r"((a)[2]), "r"((a)[3]),        \
                   "r"((b)[0]), "r"((b)[1]))

// ---------------------------------------------------------------------------
// Phase 1: Gram partials via mma.sync tf32 with 3xTF32 split.
// grid (3 sym tiles, NSPLIT, BDIM), 256 threads, CTA tile 128x128.
// Warp tile 64x32 (warps 2x4). Smem [row][k16] stride 20 (bank-clean).
// ---------------------------------------------------------------------------
__global__ void __launch_bounds__(256) gram_mma(const float* __restrict__ x) {
    __shared__ float As_h[128][20], As_l[128][20];
    __shared__ float Bs_h[128][20], Bs_l[128][20];

    const int t = blockIdx.x, split = blockIdx.y, b = blockIdx.z;
    const int ti = (t == 2) ? 1 : 0;
    const int tj = (t == 0) ? 0 : 1;
    const float* Ab = x + ((size_t)b * CDIM + ti * 128) * LDIM + (size_t)split * KCTA;
    const float* Bb = x + ((size_t)b * CDIM + tj * 128) * LDIM + (size_t)split * KCTA;

    const int tid = threadIdx.x;
    const int warp = tid >> 5, lane = tid & 31;
    const int g = lane >> 2, tg = lane & 3;
    const int m0 = (warp >> 2) * 64, n0 = (warp & 3) * 32;
    const int lrow = tid >> 2, lkq = (tid & 3) * 4;   // tile-load mapping

    float acc[4][4][4];
#pragma unroll
    for (int i = 0; i < 4; i++)
#pragma unroll
        for (int j = 0; j < 4; j++)
#pragma unroll
            for (int k = 0; k < 4; k++) acc[i][j][k] = 0.f;

    const float* A0 = Ab + (size_t)lrow * LDIM + lkq;
    const float* A1 = A0 + (size_t)64 * LDIM;
    const float* B0 = Bb + (size_t)lrow * LDIM + lkq;
    const float* B1 = B0 + (size_t)64 * LDIM;

    float4 va0 = *(const float4*)A0;
    float4 va1 = *(const float4*)A1;
    float4 vb0 = *(const float4*)B0;
    float4 vb1 = *(const float4*)B1;

    for (int kt = 0; kt < NKT_GRAM; kt++) {
        {
            const float* pv;
            float h;
#pragma unroll
            for (int j = 0; j < 4; j++) {
                pv = (const float*)&va0;
                h = tf32_hi(pv[j]);
                As_h[lrow][lkq + j] = h; As_l[lrow][lkq + j] = pv[j] - h;
                pv = (const float*)&va1;
                h = tf32_hi(pv[j]);
                As_h[lrow + 64][lkq + j] = h; As_l[lrow + 64][lkq + j] = pv[j] - h;
                pv = (const float*)&vb0;
                h = tf32_hi(pv[j]);
                Bs_h[lrow][lkq + j] = h; Bs_l[lrow][lkq + j] = pv[j] - h;
                pv = (const float*)&vb1;
                h = tf32_hi(pv[j]);
                Bs_h[lrow + 64][lkq + j] = h; Bs_l[lrow + 64][lkq + j] = pv[j] - h;
            }
        }
        __syncthreads();
        if (kt + 1 < NKT_GRAM) {
            const int ko = (kt + 1) * 16;
            va0 = *(const float4*)(A0 + ko);
            va1 = *(const float4*)(A1 + ko);
            vb0 = *(const float4*)(B0 + ko);
            vb1 = *(const float4*)(B1 + ko);
        }
#pragma unroll
        for (int s = 0; s < 2; s++) {
            const int k0 = s * 8;
            uint32_t ah[4][4], al[4][4], bh[4][2], bl[4][2];
#pragma unroll
            for (int mt = 0; mt < 4; mt++) {
                const int r = m0 + mt * 16 + g;
                ah[mt][0] = __float_as_uint(As_h[r][k0 + tg]);
                ah[mt][1] = __float_as_uint(As_h[r + 8][k0 + tg]);
                ah[mt][2] = __float_as_uint(As_h[r][k0 + tg + 4]);
                ah[mt][3] = __float_as_uint(As_h[r + 8][k0 + tg + 4]);
                al[mt][0] = __float_as_uint(As_l[r][k0 + tg]);
                al[mt][1] = __float_as_uint(As_l[r + 8][k0 + tg]);
                al[mt][2] = __float_as_uint(As_l[r][k0 + tg + 4]);
                al[mt][3] = __float_as_uint(As_l[r + 8][k0 + tg + 4]);
            }
#pragma unroll
            for (int nt = 0; nt < 4; nt++) {
                const int rn = n0 + nt * 8 + g;
                bh[nt][0] = __float_as_uint(Bs_h[rn][k0 + tg]);
                bh[nt][1] = __float_as_uint(Bs_h[rn][k0 + tg + 4]);
                bl[nt][0] = __float_as_uint(Bs_l[rn][k0 + tg]);
                bl[nt][1] = __float_as_uint(Bs_l[rn][k0 + tg + 4]);
            }
#pragma unroll
            for (int mt = 0; mt < 4; mt++)
#pragma unroll
                for (int nt = 0; nt < 4; nt++) {
                    MMA_TF32(acc[mt][nt], ah[mt], bh[nt]);
                    MMA_TF32(acc[mt][nt], ah[mt], bl[nt]);
                    MMA_TF32(acc[mt][nt], al[mt], bh[nt]);
                }
        }
        __syncthreads();
    }

    float* Cp = gP + (((size_t)b * NSPLIT + split) * 3 + t) * 16384;
#pragma unroll
    for (int mt = 0; mt < 4; mt++)
#pragma unroll
        for (int nt = 0; nt < 4; nt++) {
            const int r = m0 + mt * 16 + g;
            const int c = n0 + nt * 8 + 2 * tg;
            float2 v0; v0.x = acc[mt][nt][0]; v0.y = acc[mt][nt][1];
            float2 v1; v1.x = acc[mt][nt][2]; v1.y = acc[mt][nt][3];
            *(float2*)(Cp + (size_t)r * 128 + c) = v0;
            *(float2*)(Cp + (size_t)(r + 8) * 128 + c) = v1;
        }
}

// Reduce partials over splits into G (with mirror of the off-diagonal tile).
__global__ void gram_reduce() {
    const int idx = blockIdx.x * 256 + threadIdx.x;   // 0..49151
    const int b = blockIdx.y;
    const int t = idx >> 14;            // 0..2
    const int e = idx & 16383;
    const int i = e >> 7, j = e & 127;
    const float* p = gP + (((size_t)b * NSPLIT) * 3 + t) * 16384 + e;
    float sum = 0.f;
#pragma unroll 8
    for (int s = 0; s < NSPLIT; s++) sum += p[(size_t)s * 3 * 16384];
    const int bi = (t == 2) ? 128 : 0;
    const int bj = (t == 0) ? 0 : 128;
    gG[(size_t)b * 65536 + (size_t)(bi + i) * 256 + (bj + j)] = sum;
    if (t == 1)
        gG[(size_t)b * 65536 + (size_t)(128 + j) * 256 + i] = sum;
}

// ---------------------------------------------------------------------------
// 64x64 NT SGEMM tile for the small middle GEMMs (grid 4x4xB = 64 blocks)
// ---------------------------------------------------------------------------
struct Smem64 {
    float As[16][68];
    float Bs[16][68];
};

__device__ __forceinline__ void gemm_nt_64(Smem64& s,
                                           const float* __restrict__ A, int lda,
                                           const float* __restrict__ B, int ldb,
                                           float* __restrict__ C, int ldc) {
    const int tid = threadIdx.x;
    const int row = tid >> 2, kq = (tid & 3) * 4;
    const int tx = tid & 15, ty = tid >> 4;
    float acc[4][4] = {};
    for (int kt = 0; kt < 16; kt++) {
        float4 a = *(const float4*)(A + (size_t)row * lda + kt * 16 + kq);
        float4 bv = *(const float4*)(B + (size_t)row * ldb + kt * 16 + kq);
#pragma unroll
        for (int j = 0; j < 4; j++) {
            s.As[kq + j][row] = ((const float*)&a)[j];
            s.Bs[kq + j][row] = ((const float*)&bv)[j];
        }
        __syncthreads();
#pragma unroll
        for (int kk = 0; kk < 16; kk++) {
            float av[4], bb[4];
#pragma unroll
            for (int i = 0; i < 4; i++) av[i] = s.As[kk][ty * 4 + i];
#pragma unroll
            for (int j = 0; j < 4; j++) bb[j] = s.Bs[kk][tx * 4 + j];
#pragma unroll
            for (int i = 0; i < 4; i++)
#pragma unroll
                for (int j = 0; j < 4; j++) acc[i][j] += av[i] * bb[j];
        }
        __syncthreads();
    }
#pragma unroll
    for (int i = 0; i < 4; i++) {
        float4 v;
        v.x = acc[i][0]; v.y = acc[i][1]; v.z = acc[i][2]; v.w = acc[i][3];
        *(float4*)(C + (size_t)(ty * 4 + i) * ldc + tx * 4) = v;
    }
}

__global__ void __launch_bounds__(256) gemm_h2_kernel(const float* __restrict__ wk) {
    __shared__ Smem64 s;
    const int bx = blockIdx.x, by = blockIdx.y, b = blockIdx.z;
    gemm_nt_64(s, wk + (size_t)by * 64 * 256, 256,
               gG + (size_t)b * 65536 + (size_t)bx * 64 * 256, 256,
               gH2 + (size_t)b * 65536 + (size_t)by * 64 * 256 + bx * 64, 256);
}
__global__ void __launch_bounds__(256) gemm_attn_kernel(const float* __restrict__ wq) {
    __shared__ Smem64 s;
    const int bx = blockIdx.x, by = blockIdx.y, b = blockIdx.z;
    gemm_nt_64(s, wq + (size_t)by * 64 * 256, 256,
               gH2 + (size_t)b * 65536 + (size_t)bx * 64 * 256, 256,
               gAm + (size_t)b * 65536 + (size_t)by * 64 * 256 + bx * 64, 256);
}
__global__ void __launch_bounds__(256) gemm_m_kernel() {
    __shared__ Smem64 s;
    const int bx = blockIdx.x, by = blockIdx.y, b = blockIdx.z;
    gemm_nt_64(s, gAm + (size_t)b * 65536 + (size_t)by * 64 * 256, 256,
               gWVT + (size_t)bx * 64 * 256, 256,
               gM + (size_t)b * 65536 + (size_t)by * 64 * 256 + bx * 64, 256);
}

__global__ void transpose_wv(const float* __restrict__ wv) {
    const int c = blockIdx.x, k = threadIdx.x;
    gWVT[c * 256 + k] = wv[k * 256 + c];
}

// ---------------------------------------------------------------------------
// Softmax over q (axis=-2) for each (b, k) column, in place on gAm.
// ---------------------------------------------------------------------------
__global__ void softmax_kernel() {
    const int b = blockIdx.y;
    const int tc = threadIdx.x & 63, tq = threadIdx.x >> 6;
    const int col = blockIdx.x * 64 + tc;
    float* Ab = gAm + (size_t)b * 65536;

    float v[64];
    float m = -3.0e38f;
#pragma unroll
    for (int qi = 0; qi < 64; qi++) {
        v[qi] = Ab[(size_t)(tq + qi * 4) * 256 + col];
        m = fmaxf(m, v[qi]);
    }
    __shared__ float red[4][64];
    red[tq][tc] = m;
    __syncthreads();
    const float mm = fmaxf(fmaxf(red[0][tc], red[1][tc]),
                           fmaxf(red[2][tc], red[3][tc]));
    __syncthreads();
    float ssum = 0.f;
#pragma unroll
    for (int qi = 0; qi < 64; qi++) {
        v[qi] = expf(v[qi] - mm);
        ssum += v[qi];
    }
    red[tq][tc] = ssum;
    __syncthreads();
    const float tot = red[0][tc] + red[1][tc] + red[2][tc] + red[3][tc];
    const float inv = 1.f / tot;
#pragma unroll
    for (int qi = 0; qi < 64; qi++)
        Ab[(size_t)(tq + qi * 4) * 256 + col] = v[qi] * inv;
}

// ---------------------------------------------------------------------------
// Phase 5: y[b] = M[b] @ x[b] via mma.sync tf32, 3xTF32 split.
// CTA tile 128q x 128l, K=256.  A = M[q][k] natural; B = x tile kept in
// NATURAL [c][l] layout (row stride 136) — the transpose happens in the
// fragment-load addressing (banks 8*tg+g: conflict-free).
// grid (LDIM/128, 2, BDIM)
// ---------------------------------------------------------------------------
__global__ void __launch_bounds__(256) final_mma(const float* __restrict__ x,
                                                 float* __restrict__ y) {
    __shared__ float As_h[128][20], As_l[128][20];   // M tile [q][k16]
    __shared__ float Bs_h[16][136], Bs_l[16][136];   // x tile [c][l128]

    const int lx = blockIdx.x, qy = blockIdx.y, b = blockIdx.z;
    const float* Mb = gM + (size_t)b * 65536 + (size_t)qy * 128 * 256;
    const float* xb = x + (size_t)b * CDIM * LDIM + (size_t)lx * 128;
    float* yb = y + ((size_t)b * CDIM + (size_t)qy * 128) * LDIM + (size_t)lx * 128;

    const int tid = threadIdx.x;
    const int warp = tid >> 5, lane = tid & 31;
    const int g = lane >> 2, tg = lane & 3;
    const int m0 = (warp >> 2) * 64, n0 = (warp & 3) * 32;
    const int lrow = tid >> 2, lkq = (tid & 3) * 4;   // A-tile load mapping
    const int brow = tid >> 5, blq = (tid & 31) * 4;  // B-tile load mapping

    float acc[4][4][4];
#pragma unroll
    for (int i = 0; i < 4; i++)
#pragma unroll
        for (int j = 0; j < 4; j++)
#pragma unroll
            for (int k = 0; k < 4; k++) acc[i][j][k] = 0.f;

    const float* A0 = Mb + (size_t)lrow * 256 + lkq;
    const float* A1 = A0 + (size_t)64 * 256;
    const float* B0 = xb + (size_t)brow * LDIM + blq;
    const float* B1 = B0 + (size_t)8 * LDIM;

    float4 va0 = *(const float4*)A0;
    float4 va1 = *(const float4*)A1;
    float4 vb0 = *(const float4*)B0;
    float4 vb1 = *(const float4*)B1;

    for (int kt = 0; kt < 16; kt++) {
        {
            const float* pv;
            float h;
#pragma unroll
            for (int j = 0; j < 4; j++) {
                pv = (const float*)&va0;
                h = tf32_hi(pv[j]);
                As_h[lrow][lkq + j] = h; As_l[lrow][lkq + j] = pv[j] - h;
                pv = (const float*)&va1;
                h = tf32_hi(pv[j]);
                As_h[lrow + 64][lkq + j] = h; As_l[lrow + 64][lkq + j] = pv[j] - h;
                pv = (const float*)&vb0;
                h = tf32_hi(pv[j]);
                Bs_h[brow][blq + j] = h; Bs_l[brow][blq + j] = pv[j] - h;
                pv = (const float*)&vb1;
                h = tf32_hi(pv[j]);
                Bs_h[brow + 8][blq + j] = h; Bs_l[brow + 8][blq + j] = pv[j] - h;
            }
        }
        __syncthreads();
        if (kt + 1 < 16) {
            va0 = *(const float4*)(A0 + (kt + 1) * 16);
            va1 = *(const float4*)(A1 + (kt + 1) * 16);
            vb0 = *(const float4*)(B0 + (size_t)(kt + 1) * 16 * LDIM);
            vb1 = *(const float4*)(B1 + (size_t)(kt + 1) * 16 * LDIM);
        }
#pragma unroll
        for (int s = 0; s < 2; s++) {
            const int k0 = s * 8;
            uint32_t ah[4][4], al[4][4], bh[4][2], bl[4][2];
#pragma unroll
            for (int mt = 0; mt < 4; mt++) {
                const int r = m0 + mt * 16 + g;
                ah[mt][0] = __float_as_uint(As_h[r][k0 + tg]);
                ah[mt][1] = __float_as_uint(As_h[r + 8][k0 + tg]);
                ah[mt][2] = __float_as_uint(As_h[r][k0 + tg + 4]);
                ah[mt][3] = __float_as_uint(As_h[r + 8][k0 + tg + 4]);
                al[mt][0] = __float_as_uint(As_l[r][k0 + tg]);
                al[mt][1] = __float_as_uint(As_l[r + 8][k0 + tg]);
                al[mt][2] = __float_as_uint(As_l[r][k0 + tg + 4]);
                al[mt][3] = __float_as_uint(As_l[r + 8][k0 + tg + 4]);
            }
#pragma unroll
            for (int nt = 0; nt < 4; nt++) {
                const int cn = n0 + nt * 8 + g;
                bh[nt][0] = __float_as_uint(Bs_h[k0 + tg][cn]);
                bh[nt][1] = __float_as_uint(Bs_h[k0 + tg + 4][cn]);
                bl[nt][0] = __float_as_uint(Bs_l[k0 + tg][cn]);
                bl[nt][1] = __float_as_uint(Bs_l[k0 + tg + 4][cn]);
            }
#pragma unroll
            for (int mt = 0; mt < 4; mt++)
#pragma unroll
                for (int nt = 0; nt < 4; nt++) {
                    MMA_TF32(acc[mt][nt], ah[mt], bh[nt]);
                    MMA_TF32(acc[mt][nt], ah[mt], bl[nt]);
                    MMA_TF32(acc[mt][nt], al[mt], bh[nt]);
                }
        }
        __syncthreads();
    }

#pragma unroll
    for (int mt = 0; mt < 4; mt++)
#pragma unroll
        for (int nt = 0; nt < 4; nt++) {
            const int r = m0 + mt * 16 + g;
            const int c = n0 + nt * 8 + 2 * tg;
            float2 v0; v0.x = acc[mt][nt][0]; v0.y = acc[mt][nt][1];
            float2 v1; v1.x = acc[mt][nt][2]; v1.y = acc[mt][nt][3];
            *(float2*)(yb + (size_t)r * LDIM + c) = v0;
            *(float2*)(yb + (size_t)(r + 8) * LDIM + c) = v1;
        }
}

// ---------------------------------------------------------------------------
// Launch
// ---------------------------------------------------------------------------
extern "C" void kernel_launch(void* const* d_in, const int* in_sizes, int n_in,
                              void* d_out, int out_size) {
    const float *x = nullptr, *wq = nullptr, *wk = nullptr, *wv = nullptr;
    for (int i = 0; i < n_in; i++) {
        if (in_sizes[i] == BDIM * CDIM * LDIM) {
            x = (const float*)d_in[i];
        } else if (!wq) wq = (const float*)d_in[i];
        else if (!wk) wk = (const float*)d_in[i];
        else wv = (const float*)d_in[i];
    }
    float* y = (float*)d_out;

    gram_mma<<<dim3(3, NSPLIT, BDIM), 256>>>(x);
    gram_reduce<<<dim3(192, BDIM), 256>>>();
    transpose_wv<<<256, 256>>>(wv);
    gemm_h2_kernel<<<dim3(4, 4, BDIM), 256>>>(wk);
    gemm_attn_kernel<<<dim3(4, 4, BDIM), 256>>>(wq);
    softmax_kernel<<<dim3(4, BDIM), 256>>>();
    gemm_m_kernel<<<dim3(4, 4, BDIM), 256>>>();
    final_mma<<<dim3(LDIM / 128, 2, BDIM), 256>>>(x, y);
}

// round 8
// speedup vs baseline: 1.6379x; 1.2525x over previous
#include <cuda_runtime.h>
#include <cstdint>
#include <math.h>

// Problem constants
#define BDIM 4
#define CDIM 256
#define LDIM 32768

// Gram split-K
#define NSPLIT 32
#define KCTA   (LDIM / NSPLIT)   // 1024
#define NKT_GRAM (KCTA / 16)     // 64 k-steps of 16

// ---------------------------------------------------------------------------
// Scratch (static device arrays)
// ---------------------------------------------------------------------------
__device__ float gP[BDIM * NSPLIT * 3 * 128 * 128];  // partial Gram tiles (25MB)
__device__ float gG[BDIM * CDIM * CDIM];             // G = x x^T
__device__ float gH2[BDIM * CDIM * CDIM];            // H2 = W_K * G
__device__ float gAm[BDIM * CDIM * CDIM];            // logits -> softmax
__device__ float gM[BDIM * CDIM * CDIM];             // M = A * W_V
__device__ float gWVT[CDIM * CDIM];                  // W_V transposed

// ---------------------------------------------------------------------------
// mma.sync tf32 (sm_80+ PTX — works under compute_100)
// ---------------------------------------------------------------------------
__device__ __forceinline__ float tf32_hi(float v) {
    uint32_t u;
    asm("cvt.rna.tf32.f32 %0, %1;" : "=r"(u) : "f"(v));
    return __uint_as_float(u);
}

#define MMA_TF32(c, a, b)                                                     \
    asm volatile("mma.sync.aligned.m16n8k8.row.col.f32.tf32.tf32.f32 "        \
                 "{%0,%1,%2,%3}, {%4,%5,%6,%7}, {%8,%9}, {%0,%1,%2,%3};"      \
                 : "+f"((c)[0]), "+f"((c)[1]), "+f"((c)[2]), "+f"((c)[3])     \
                 : "r"((a)[0]), "r"((a)[1]), "r"((a)[2]), "r"((a)[3]),        \
                   "r"((b)[0]), "r"((b)[1]))

// ---------------------------------------------------------------------------
// Phase 1: Gram partials via mma.sync tf32, 3xTF32 split (needed upstream of
// softmax). (hi,lo) interleaved as float2 in smem -> LDS.64 fragment loads.
// grid (3 sym tiles, NSPLIT, BDIM), 256 threads, CTA tile 128x128.
// Row stride 18 float2: banks (18g+tg) mod 16 are <=2-way (free for 64-bit).
// ---------------------------------------------------------------------------
__global__ void __launch_bounds__(256) gram_mma(const float* __restrict__ x) {
    __shared__ float2 As2[128][18];
    __shared__ float2 Bs2[128][18];

    const int t = blockIdx.x, split = blockIdx.y, b = blockIdx.z;
    const int ti = (t == 2) ? 1 : 0;
    const int tj = (t == 0) ? 0 : 1;
    const float* Ab = x + ((size_t)b * CDIM + ti * 128) * LDIM + (size_t)split * KCTA;
    const float* Bb = x + ((size_t)b * CDIM + tj * 128) * LDIM + (size_t)split * KCTA;

    const int tid = threadIdx.x;
    const int warp = tid >> 5, lane = tid & 31;
    const int g = lane >> 2, tg = lane & 3;
    const int m0 = (warp >> 2) * 64, n0 = (warp & 3) * 32;
    const int lrow = tid >> 2, lkq = (tid & 3) * 4;

    float acc[4][4][4];
#pragma unroll
    for (int i = 0; i < 4; i++)
#pragma unroll
        for (int j = 0; j < 4; j++)
#pragma unroll
            for (int k = 0; k < 4; k++) acc[i][j][k] = 0.f;

    const float* A0 = Ab + (size_t)lrow * LDIM + lkq;
    const float* A1 = A0 + (size_t)64 * LDIM;
    const float* B0 = Bb + (size_t)lrow * LDIM + lkq;
    const float* B1 = B0 + (size_t)64 * LDIM;

    float4 va0 = *(const float4*)A0;
    float4 va1 = *(const float4*)A1;
    float4 vb0 = *(const float4*)B0;
    float4 vb1 = *(const float4*)B1;

    for (int kt = 0; kt < NKT_GRAM; kt++) {
        {
            const float* pv;
            float h;
#pragma unroll
            for (int j = 0; j < 4; j++) {
                pv = (const float*)&va0;
                h = tf32_hi(pv[j]);
                As2[lrow][lkq + j] = make_float2(h, pv[j] - h);
                pv = (const float*)&va1;
                h = tf32_hi(pv[j]);
                As2[lrow + 64][lkq + j] = make_float2(h, pv[j] - h);
                pv = (const float*)&vb0;
                h = tf32_hi(pv[j]);
                Bs2[lrow][lkq + j] = make_float2(h, pv[j] - h);
                pv = (const float*)&vb1;
                h = tf32_hi(pv[j]);
                Bs2[lrow + 64][lkq + j] = make_float2(h, pv[j] - h);
            }
        }
        __syncthreads();
        if (kt + 1 < NKT_GRAM) {
            const int ko = (kt + 1) * 16;
            va0 = *(const float4*)(A0 + ko);
            va1 = *(const float4*)(A1 + ko);
            vb0 = *(const float4*)(B0 + ko);
            vb1 = *(const float4*)(B1 + ko);
        }
#pragma unroll
        for (int s = 0; s < 2; s++) {
            const int k0 = s * 8;
            uint32_t ah[4][4], al[4][4], bh[4][2], bl[4][2];
#pragma unroll
            for (int mt = 0; mt < 4; mt++) {
                const int r = m0 + mt * 16 + g;
                float2 p0 = As2[r][k0 + tg];
                float2 p1 = As2[r + 8][k0 + tg];
                float2 p2 = As2[r][k0 + tg + 4];
                float2 p3 = As2[r + 8][k0 + tg + 4];
                ah[mt][0] = __float_as_uint(p0.x); al[mt][0] = __float_as_uint(p0.y);
                ah[mt][1] = __float_as_uint(p1.x); al[mt][1] = __float_as_uint(p1.y);
                ah[mt][2] = __float_as_uint(p2.x); al[mt][2] = __float_as_uint(p2.y);
                ah[mt][3] = __float_as_uint(p3.x); al[mt][3] = __float_as_uint(p3.y);
            }
#pragma unroll
            for (int nt = 0; nt < 4; nt++) {
                const int rn = n0 + nt * 8 + g;
                float2 q0 = Bs2[rn][k0 + tg];
                float2 q1 = Bs2[rn][k0 + tg + 4];
                bh[nt][0] = __float_as_uint(q0.x); bl[nt][0] = __float_as_uint(q0.y);
                bh[nt][1] = __float_as_uint(q1.x); bl[nt][1] = __float_as_uint(q1.y);
            }
#pragma unroll
            for (int mt = 0; mt < 4; mt++)
#pragma unroll
                for (int nt = 0; nt < 4; nt++) {
                    MMA_TF32(acc[mt][nt], ah[mt], bh[nt]);
                    MMA_TF32(acc[mt][nt], ah[mt], bl[nt]);
                    MMA_TF32(acc[mt][nt], al[mt], bh[nt]);
                }
        }
        __syncthreads();
    }

    float* Cp = gP + (((size_t)b * NSPLIT + split) * 3 + t) * 16384;
#pragma unroll
    for (int mt = 0; mt < 4; mt++)
#pragma unroll
        for (int nt = 0; nt < 4; nt++) {
            const int r = m0 + mt * 16 + g;
            const int c = n0 + nt * 8 + 2 * tg;
            float2 v0; v0.x = acc[mt][nt][0]; v0.y = acc[mt][nt][1];
            float2 v1; v1.x = acc[mt][nt][2]; v1.y = acc[mt][nt][3];
            *(float2*)(Cp + (size_t)r * 128 + c) = v0;
            *(float2*)(Cp + (size_t)(r + 8) * 128 + c) = v1;
        }
}

// Reduce partials over splits into G (with mirror of the off-diagonal tile).
__global__ void gram_reduce() {
    const int idx = blockIdx.x * 256 + threadIdx.x;   // 0..49151
    const int b = blockIdx.y;
    const int t = idx >> 14;
    const int e = idx & 16383;
    const int i = e >> 7, j = e & 127;
    const float* p = gP + (((size_t)b * NSPLIT) * 3 + t) * 16384 + e;
    float sum = 0.f;
#pragma unroll 8
    for (int s = 0; s < NSPLIT; s++) sum += p[(size_t)s * 3 * 16384];
    const int bi = (t == 2) ? 128 : 0;
    const int bj = (t == 0) ? 0 : 128;
    gG[(size_t)b * 65536 + (size_t)(bi + i) * 256 + (bj + j)] = sum;
    if (t == 1)
        gG[(size_t)b * 65536 + (size_t)(128 + j) * 256 + i] = sum;
}

// ---------------------------------------------------------------------------
// 32x64 NT SGEMM tile for the small middle GEMMs (grid 8x4xB = 128 blocks)
// ---------------------------------------------------------------------------
struct Smem3264 {
    float As[16][36];
    float Bs[16][68];
};

__device__ __forceinline__ void gemm_nt_3264(Smem3264& s,
                                             const float* __restrict__ A,
                                             const float* __restrict__ B,
                                             float* __restrict__ C) {
    const int tid = threadIdx.x;
    const int row = tid >> 2, kq = (tid & 3) * 4;
    const int tx = tid & 15, ty = tid >> 4;
    const int n0 = tx * 4, m0 = ty * 2;
    float acc[2][4] = {};
    for (int kt = 0; kt < 16; kt++) {
        if (tid < 128) {
            float4 a = *(const float4*)(A + (size_t)row * 256 + kt * 16 + kq);
#pragma unroll
            for (int j = 0; j < 4; j++) s.As[kq + j][row] = ((const float*)&a)[j];
        }
        float4 bv = *(const float4*)(B + (size_t)row * 256 + kt * 16 + kq);
#pragma unroll
        for (int j = 0; j < 4; j++) s.Bs[kq + j][row] = ((const float*)&bv)[j];
        __syncthreads();
#pragma unroll
        for (int kk = 0; kk < 16; kk++) {
            const float av0 = s.As[kk][m0];
            const float av1 = s.As[kk][m0 + 1];
#pragma unroll
            for (int j = 0; j < 4; j++) {
                const float bb = s.Bs[kk][n0 + j];
                acc[0][j] += av0 * bb;
                acc[1][j] += av1 * bb;
            }
        }
        __syncthreads();
    }
#pragma unroll
    for (int i = 0; i < 2; i++) {
        float4 v;
        v.x = acc[i][0]; v.y = acc[i][1]; v.z = acc[i][2]; v.w = acc[i][3];
        *(float4*)(C + (size_t)(m0 + i) * 256 + n0) = v;
    }
}

__global__ void __launch_bounds__(256) gemm_h2_kernel(const float* __restrict__ wk) {
    __shared__ Smem3264 s;
    const int bx = blockIdx.x, by = blockIdx.y, b = blockIdx.z;
    gemm_nt_3264(s, wk + (size_t)bx * 32 * 256,
                 gG + (size_t)b * 65536 + (size_t)by * 64 * 256,
                 gH2 + (size_t)b * 65536 + (size_t)bx * 32 * 256 + by * 64);
}
__global__ void __launch_bounds__(256) gemm_attn_kernel(const float* __restrict__ wq) {
    __shared__ Smem3264 s;
    const int bx = blockIdx.x, by = blockIdx.y, b = blockIdx.z;
    gemm_nt_3264(s, wq + (size_t)bx * 32 * 256,
                 gH2 + (size_t)b * 65536 + (size_t)by * 64 * 256,
                 gAm + (size_t)b * 65536 + (size_t)bx * 32 * 256 + by * 64);
}
__global__ void __launch_bounds__(256) gemm_m_kernel() {
    __shared__ Smem3264 s;
    const int bx = blockIdx.x, by = blockIdx.y, b = blockIdx.z;
    gemm_nt_3264(s, gAm + (size_t)b * 65536 + (size_t)bx * 32 * 256,
                 gWVT + (size_t)by * 64 * 256,
                 gM + (size_t)b * 65536 + (size_t)bx * 32 * 256 + by * 64);
}

__global__ void transpose_wv(const float* __restrict__ wv) {
    const int c = blockIdx.x, k = threadIdx.x;
    gWVT[c * 256 + k] = wv[k * 256 + c];
}

// ---------------------------------------------------------------------------
// Softmax over q (axis=-2), grid (16, B): 16 cols/block, 16 q per thread.
// ---------------------------------------------------------------------------
__global__ void __launch_bounds__(256) softmax_kernel() {
    const int b = blockIdx.y;
    const int tc = threadIdx.x & 15, tq = threadIdx.x >> 4;
    const int col = blockIdx.x * 16 + tc;
    float* Ab = gAm + (size_t)b * 65536;

    float v[16];
    float m = -3.0e38f;
#pragma unroll
    for (int qi = 0; qi < 16; qi++) {
        v[qi] = Ab[(size_t)(tq + qi * 16) * 256 + col];
        m = fmaxf(m, v[qi]);
    }
    __shared__ float red[16][16];
    red[tq][tc] = m;
    __syncthreads();
    float mm = red[0][tc];
#pragma unroll
    for (int r = 1; r < 16; r++) mm = fmaxf(mm, red[r][tc]);
    __syncthreads();
    float ssum = 0.f;
#pragma unroll
    for (int qi = 0; qi < 16; qi++) {
        v[qi] = expf(v[qi] - mm);
        ssum += v[qi];
    }
    red[tq][tc] = ssum;
    __syncthreads();
    float tot = 0.f;
#pragma unroll
    for (int r = 0; r < 16; r++) tot += red[r][tc];
    const float inv = 1.f / tot;
#pragma unroll
    for (int qi = 0; qi < 16; qi++)
        Ab[(size_t)(tq + qi * 16) * 256 + col] = v[qi] * inv;
}

// ---------------------------------------------------------------------------
// Phase 5: y[b] = M[b] @ x[b] via mma.sync, 1x TF32 (downstream of softmax:
// tf32 eps ~5e-4 norm-wise, within the 1e-3 gate).
// A = M tile [q][k], packed as (k, k+4) float2 pairs -> LDS.64 frag loads
// (stride 10 float2: banks (10g+tg) mod 16 perfectly 2-way = free).
// B = x tile kept NATURAL [c][l] (row stride 136); transpose happens in the
// fragment addressing. grid (LDIM/128, 2, BDIM).
// ---------------------------------------------------------------------------
__global__ void __launch_bounds__(256) final_mma(const float* __restrict__ x,
                                                 float* __restrict__ y) {
    __shared__ float2 Ap[128][10];     // slot j: j<4 -> (k=j, k=j+4); j>=4 -> (k=j+4, k=j+8)
    __shared__ float Bs[16][136];      // x tile [c][l128], tf32-rounded

    const int lx = blockIdx.x, qy = blockIdx.y, b = blockIdx.z;
    const float* Mb = gM + (size_t)b * 65536 + (size_t)qy * 128 * 256;
    const float* xb = x + (size_t)b * CDIM * LDIM + (size_t)lx * 128;
    float* yb = y + ((size_t)b * CDIM + (size_t)qy * 128) * LDIM + (size_t)lx * 128;

    const int tid = threadIdx.x;
    const int warp = tid >> 5, lane = tid & 31;
    const int g = lane >> 2, tg = lane & 3;
    const int m0 = (warp >> 2) * 64, n0 = (warp & 3) * 32;
    const int lrow = tid >> 2, lkq = (tid & 3) * 4;   // A-tile load mapping
    const int brow = tid >> 5, blq = (tid & 31) * 4;  // B-tile load mapping

    // A store mapping: cols c = lkq..lkq+3 share slot base and component
    const int aslot0 = (lkq >= 8) ? 4 : 0;            // lkq in {0,4,8,12}
    const int acomp = ((lkq >> 2) & 1);

    float acc[4][4][4];
#pragma unroll
    for (int i = 0; i < 4; i++)
#pragma unroll
        for (int j = 0; j < 4; j++)
#pragma unroll
            for (int k = 0; k < 4; k++) acc[i][j][k] = 0.f;

    const float* A0 = Mb + (size_t)lrow * 256 + lkq;
    const float* A1 = A0 + (size_t)64 * 256;
    const float* B0 = xb + (size_t)brow * LDIM + blq;
    const float* B1 = B0 + (size_t)8 * LDIM;

    float4 va0 = *(const float4*)A0;
    float4 va1 = *(const float4*)A1;
    float4 vb0 = *(const float4*)B0;
    float4 vb1 = *(const float4*)B1;

    for (int kt = 0; kt < 16; kt++) {
        {
            float* a0p = (float*)&Ap[lrow][aslot0];
            float* a1p = (float*)&Ap[lrow + 64][aslot0];
#pragma unroll
            for (int j = 0; j < 4; j++) {
                a0p[2 * j + acomp] = tf32_hi(((const float*)&va0)[j]);
                a1p[2 * j + acomp] = tf32_hi(((const float*)&va1)[j]);
                Bs[brow][blq + j] = tf32_hi(((const float*)&vb0)[j]);
                Bs[brow + 8][blq + j] = tf32_hi(((const float*)&vb1)[j]);
            }
        }
        __syncthreads();
        if (kt + 1 < 16) {
            va0 = *(const float4*)(A0 + (kt + 1) * 16);
            va1 = *(const float4*)(A1 + (kt + 1) * 16);
            vb0 = *(const float4*)(B0 + (size_t)(kt + 1) * 16 * LDIM);
            vb1 = *(const float4*)(B1 + (size_t)(kt + 1) * 16 * LDIM);
        }
#pragma unroll
        for (int s = 0; s < 2; s++) {
            const int k0 = s * 8;
            const int sl = s * 4 + tg;
            uint32_t ah[4][4], bh[4][2];
#pragma unroll
            for (int mt = 0; mt < 4; mt++) {
                const int r = m0 + mt * 16 + g;
                float2 p0 = Ap[r][sl];        // (A[r][k0+tg], A[r][k0+tg+4])
                float2 p1 = Ap[r + 8][sl];
                ah[mt][0] = __float_as_uint(p0.x);
                ah[mt][1] = __float_as_uint(p1.x);
                ah[mt][2] = __float_as_uint(p0.y);
                ah[mt][3] = __float_as_uint(p1.y);
            }
#pragma unroll
            for (int nt = 0; nt < 4; nt++) {
                const int cn = n0 + nt * 8 + g;
                bh[nt][0] = __float_as_uint(Bs[k0 + tg][cn]);
                bh[nt][1] = __float_as_uint(Bs[k0 + tg + 4][cn]);
            }
#pragma unroll
            for (int mt = 0; mt < 4; mt++)
#pragma unroll
                for (int nt = 0; nt < 4; nt++)
                    MMA_TF32(acc[mt][nt], ah[mt], bh[nt]);
        }
        __syncthreads();
    }

#pragma unroll
    for (int mt = 0; mt < 4; mt++)
#pragma unroll
        for (int nt = 0; nt < 4; nt++) {
            const int r = m0 + mt * 16 + g;
            const int c = n0 + nt * 8 + 2 * tg;
            float2 v0; v0.x = acc[mt][nt][0]; v0.y = acc[mt][nt][1];
            float2 v1; v1.x = acc[mt][nt][2]; v1.y = acc[mt][nt][3];
            *(float2*)(yb + (size_t)r * LDIM + c) = v0;
            *(float2*)(yb + (size_t)(r + 8) * LDIM + c) = v1;
        }
}

// ---------------------------------------------------------------------------
// Launch
// ---------------------------------------------------------------------------
extern "C" void kernel_launch(void* const* d_in, const int* in_sizes, int n_in,
                              void* d_out, int out_size) {
    const float *x = nullptr, *wq = nullptr, *wk = nullptr, *wv = nullptr;
    for (int i = 0; i < n_in; i++) {
        if (in_sizes[i] == BDIM * CDIM * LDIM) {
            x = (const float*)d_in[i];
        } else if (!wq) wq = (const float*)d_in[i];
        else if (!wk) wk = (const float*)d_in[i];
        else wv = (const float*)d_in[i];
    }
    float* y = (float*)d_out;

    gram_mma<<<dim3(3, NSPLIT, BDIM), 256>>>(x);
    gram_reduce<<<dim3(192, BDIM), 256>>>();
    transpose_wv<<<256, 256>>>(wv);
    gemm_h2_kernel<<<dim3(8, 4, BDIM), 256>>>(wk);
    gemm_attn_kernel<<<dim3(8, 4, BDIM), 256>>>(wq);
    softmax_kernel<<<dim3(16, BDIM), 256>>>();
    gemm_m_kernel<<<dim3(8, 4, BDIM), 256>>>();
    final_mma<<<dim3(LDIM / 128, 2, BDIM), 256>>>(x, y);
}

// round 9
// speedup vs baseline: 1.8680x; 1.1405x over previous
#include <cuda_runtime.h>
#include <cstdint>
#include <math.h>

// Problem constants
#define BDIM 4
#define CDIM 256
#define LDIM 32768

// Gram split-K
#define NSPLIT 32
#define KCTA   (LDIM / NSPLIT)   // 1024
#define NKT_GRAM (KCTA / 16)     // 64 k-steps of 16

// ---------------------------------------------------------------------------
// Scratch (static device arrays)
// ---------------------------------------------------------------------------
__device__ float gP[BDIM * NSPLIT * 3 * 128 * 128];  // partial Gram tiles (25MB)
__device__ float gG[BDIM * CDIM * CDIM];             // G = x x^T
__device__ float gH2[BDIM * CDIM * CDIM];            // H2 = W_K * G
__device__ float gAm[BDIM * CDIM * CDIM];            // logits -> softmax
__device__ float gM[BDIM * CDIM * CDIM];             // M = A * W_V

// ---------------------------------------------------------------------------
// mma.sync tf32 (sm_80+ PTX — works under compute_100)
// ---------------------------------------------------------------------------
__device__ __forceinline__ float tf32_hi(float v) {
    uint32_t u;
    asm("cvt.rna.tf32.f32 %0, %1;" : "=r"(u) : "f"(v));
    return __uint_as_float(u);
}

#define MMA_TF32(c, a, b)                                                     \
    asm volatile("mma.sync.aligned.m16n8k8.row.col.f32.tf32.tf32.f32 "        \
                 "{%0,%1,%2,%3}, {%4,%5,%6,%7}, {%8,%9}, {%0,%1,%2,%3};"      \
                 : "+f"((c)[0]), "+f"((c)[1]), "+f"((c)[2]), "+f"((c)[3])     \
                 : "r"((a)[0]), "r"((a)[1]), "r"((a)[2]), "r"((a)[3]),        \
                   "r"((b)[0]), "r"((b)[1]))

// ---------------------------------------------------------------------------
// Phase 1: Gram partials via mma.sync tf32, 3xTF32-equivalent accuracy.
// Smem stores (hi/2, lo) pairs.
//  - Off-diag tile (t=1): hi reconstructed as 2*(hi/2); 3 products as before.
//  - Diag tiles (t=0,2): A==B, so store ONLY As2 and compute
//      acc = (hi/2)*hi + hi*lo ;  G = acc + acc^T  (sym_diag kernel later)
//    -> 2 MMAs instead of 3, no B loads/stores at all.
// grid (3, NSPLIT, BDIM), 256 threads, CTA tile 128x128, warp tile 64x32.
// ---------------------------------------------------------------------------
__global__ void __launch_bounds__(256, 2) gram_mma(const float* __restrict__ x) {
    __shared__ float2 As2[128][18];
    __shared__ float2 Bs2[128][18];

    const int t = blockIdx.x, split = blockIdx.y, b = blockIdx.z;
    const bool diag = (t != 1);
    const int ti = (t == 2) ? 1 : 0;
    const int tj = (t == 0) ? 0 : 1;
    const float* Ab = x + ((size_t)b * CDIM + ti * 128) * LDIM + (size_t)split * KCTA;
    const float* Bb = x + ((size_t)b * CDIM + tj * 128) * LDIM + (size_t)split * KCTA;

    const int tid = threadIdx.x;
    const int warp = tid >> 5, lane = tid & 31;
    const int g = lane >> 2, tg = lane & 3;
    const int m0 = (warp >> 2) * 64, n0 = (warp & 3) * 32;
    const int lrow = tid >> 2, lkq = (tid & 3) * 4;

    float acc[4][4][4];
#pragma unroll
    for (int i = 0; i < 4; i++)
#pragma unroll
        for (int j = 0; j < 4; j++)
#pragma unroll
            for (int k = 0; k < 4; k++) acc[i][j][k] = 0.f;

    const float* A0 = Ab + (size_t)lrow * LDIM + lkq;
    const float* A1 = A0 + (size_t)64 * LDIM;
    const float* B0 = Bb + (size_t)lrow * LDIM + lkq;
    const float* B1 = B0 + (size_t)64 * LDIM;

    float4 va0 = *(const float4*)A0;
    float4 va1 = *(const float4*)A1;
    float4 vb0, vb1;
    if (!diag) { vb0 = *(const float4*)B0; vb1 = *(const float4*)B1; }

    for (int kt = 0; kt < NKT_GRAM; kt++) {
#pragma unroll
        for (int j = 0; j < 4; j++) {
            float v = ((const float*)&va0)[j];
            float h = tf32_hi(v);
            As2[lrow][lkq + j] = make_float2(0.5f * h, v - h);
            v = ((const float*)&va1)[j];
            h = tf32_hi(v);
            As2[lrow + 64][lkq + j] = make_float2(0.5f * h, v - h);
        }
        if (!diag) {
#pragma unroll
            for (int j = 0; j < 4; j++) {
                float v = ((const float*)&vb0)[j];
                float h = tf32_hi(v);
                Bs2[lrow][lkq + j] = make_float2(0.5f * h, v - h);
                v = ((const float*)&vb1)[j];
                h = tf32_hi(v);
                Bs2[lrow + 64][lkq + j] = make_float2(0.5f * h, v - h);
            }
        }
        __syncthreads();
        if (kt + 1 < NKT_GRAM) {
            const int ko = (kt + 1) * 16;
            va0 = *(const float4*)(A0 + ko);
            va1 = *(const float4*)(A1 + ko);
            if (!diag) {
                vb0 = *(const float4*)(B0 + ko);
                vb1 = *(const float4*)(B1 + ko);
            }
        }
        const float2 (*Bsrc)[18] = diag ? As2 : Bs2;
#pragma unroll
        for (int s = 0; s < 2; s++) {
            const int k0 = s * 8;
            if (diag) {
                uint32_t af[4][4], bh[4][2], bl[4][2];
#pragma unroll
                for (int mt = 0; mt < 4; mt++) {
                    const int r = m0 + mt * 16 + g;
                    float2 p0 = As2[r][k0 + tg];
                    float2 p1 = As2[r + 8][k0 + tg];
                    float2 p2 = As2[r][k0 + tg + 4];
                    float2 p3 = As2[r + 8][k0 + tg + 4];
                    af[mt][0] = __float_as_uint(p0.x);   // hi/2
                    af[mt][1] = __float_as_uint(p1.x);
                    af[mt][2] = __float_as_uint(p2.x);
                    af[mt][3] = __float_as_uint(p3.x);
                }
#pragma unroll
                for (int nt = 0; nt < 4; nt++) {
                    const int rn = n0 + nt * 8 + g;
                    float2 q0 = Bsrc[rn][k0 + tg];
                    float2 q1 = Bsrc[rn][k0 + tg + 4];
                    bh[nt][0] = __float_as_uint(2.f * q0.x);  // hi
                    bh[nt][1] = __float_as_uint(2.f * q1.x);
                    bl[nt][0] = __float_as_uint(q0.y);        // lo
                    bl[nt][1] = __float_as_uint(q1.y);
                }
                // product 1: (hi/2) * hi
#pragma unroll
                for (int mt = 0; mt < 4; mt++)
#pragma unroll
                    for (int nt = 0; nt < 4; nt++)
                        MMA_TF32(acc[mt][nt], af[mt], bh[nt]);
                // af <- hi  (2 * hi/2, exact)
#pragma unroll
                for (int mt = 0; mt < 4; mt++)
#pragma unroll
                    for (int q = 0; q < 4; q++)
                        af[mt][q] = __float_as_uint(2.f * __uint_as_float(af[mt][q]));
                // product 2: hi * lo
#pragma unroll
                for (int mt = 0; mt < 4; mt++)
#pragma unroll
                    for (int nt = 0; nt < 4; nt++)
                        MMA_TF32(acc[mt][nt], af[mt], bl[nt]);
            } else {
                uint32_t ah[4][4], al[4][4], bh[4][2], bl[4][2];
#pragma unroll
                for (int mt = 0; mt < 4; mt++) {
                    const int r = m0 + mt * 16 + g;
                    float2 p0 = As2[r][k0 + tg];
                    float2 p1 = As2[r + 8][k0 + tg];
                    float2 p2 = As2[r][k0 + tg + 4];
                    float2 p3 = As2[r + 8][k0 + tg + 4];
                    ah[mt][0] = __float_as_uint(2.f * p0.x);
                    ah[mt][1] = __float_as_uint(2.f * p1.x);
                    ah[mt][2] = __float_as_uint(2.f * p2.x);
                    ah[mt][3] = __float_as_uint(2.f * p3.x);
                    al[mt][0] = __float_as_uint(p0.y);
                    al[mt][1] = __float_as_uint(p1.y);
                    al[mt][2] = __float_as_uint(p2.y);
                    al[mt][3] = __float_as_uint(p3.y);
                }
#pragma unroll
                for (int nt = 0; nt < 4; nt++) {
                    const int rn = n0 + nt * 8 + g;
                    float2 q0 = Bsrc[rn][k0 + tg];
                    float2 q1 = Bsrc[rn][k0 + tg + 4];
                    bh[nt][0] = __float_as_uint(2.f * q0.x);
                    bh[nt][1] = __float_as_uint(2.f * q1.x);
                    bl[nt][0] = __float_as_uint(q0.y);
                    bl[nt][1] = __float_as_uint(q1.y);
                }
#pragma unroll
                for (int mt = 0; mt < 4; mt++)
#pragma unroll
                    for (int nt = 0; nt < 4; nt++) {
                        MMA_TF32(acc[mt][nt], ah[mt], bh[nt]);
                        MMA_TF32(acc[mt][nt], ah[mt], bl[nt]);
                        MMA_TF32(acc[mt][nt], al[mt], bh[nt]);
                    }
            }
        }
        __syncthreads();
    }

    float* Cp = gP + (((size_t)b * NSPLIT + split) * 3 + t) * 16384;
#pragma unroll
    for (int mt = 0; mt < 4; mt++)
#pragma unroll
        for (int nt = 0; nt < 4; nt++) {
            const int r = m0 + mt * 16 + g;
            const int c = n0 + nt * 8 + 2 * tg;
            float2 v0; v0.x = acc[mt][nt][0]; v0.y = acc[mt][nt][1];
            float2 v1; v1.x = acc[mt][nt][2]; v1.y = acc[mt][nt][3];
            *(float2*)(Cp + (size_t)r * 128 + c) = v0;
            *(float2*)(Cp + (size_t)(r + 8) * 128 + c) = v1;
        }
}

// Reduce partials over splits into G. Diag tiles get raw sums (symmetrized
// by sym_diag next); off-diag tile mirrored as before.
__global__ void gram_reduce() {
    const int idx = blockIdx.x * 256 + threadIdx.x;   // 0..49151
    const int b = blockIdx.y;
    const int t = idx >> 14;
    const int e = idx & 16383;
    const int i = e >> 7, j = e & 127;
    const float* p = gP + (((size_t)b * NSPLIT) * 3 + t) * 16384 + e;
    float sum = 0.f;
#pragma unroll 8
    for (int s = 0; s < NSPLIT; s++) sum += p[(size_t)s * 3 * 16384];
    float* Gb = gG + (size_t)b * 65536;
    if (t == 0) {
        Gb[(size_t)i * 256 + j] = sum;
    } else if (t == 2) {
        Gb[(size_t)(128 + i) * 256 + (128 + j)] = sum;
    } else {
        Gb[(size_t)i * 256 + (128 + j)] = sum;
        Gb[(size_t)(128 + j) * 256 + i] = sum;
    }
}

// Symmetrize diag blocks in place: G[p][q] = Graw[p][q] + Graw[q][p].
// grid (10 subtile pairs, 2 diag blocks, BDIM), 256 threads.
__global__ void sym_diag() {
    const int pu[10] = {0, 0, 0, 0, 1, 1, 1, 2, 2, 3};
    const int pv[10] = {0, 1, 2, 3, 1, 2, 3, 2, 3, 3};
    const int pr = blockIdx.x, dblk = blockIdx.y, b = blockIdx.z;
    const int u = pu[pr], v = pv[pr];
    const int base = dblk * 128;
    float* Gb = gG + (size_t)b * 65536;
    __shared__ float Ta[32][33], Tb[32][33];
    const int r = threadIdx.x >> 3, c4 = (threadIdx.x & 7) * 4;
    const int ar = base + u * 32, ac = base + v * 32;
    const int br = base + v * 32, bc = base + u * 32;
    float4 a = *(const float4*)(Gb + (size_t)(ar + r) * 256 + ac + c4);
    float4 bq = *(const float4*)(Gb + (size_t)(br + r) * 256 + bc + c4);
#pragma unroll
    for (int j = 0; j < 4; j++) {
        Ta[r][c4 + j] = ((const float*)&a)[j];
        Tb[r][c4 + j] = ((const float*)&bq)[j];
    }
    __syncthreads();
    float4 o1, o2;
#pragma unroll
    for (int j = 0; j < 4; j++) {
        ((float*)&o1)[j] = Ta[r][c4 + j] + Tb[c4 + j][r];
        ((float*)&o2)[j] = Tb[r][c4 + j] + Ta[c4 + j][r];
    }
    *(float4*)(Gb + (size_t)(ar + r) * 256 + ac + c4) = o1;
    if (u != v)
        *(float4*)(Gb + (size_t)(br + r) * 256 + bc + c4) = o2;
}

// ---------------------------------------------------------------------------
// 32x64 SGEMM tiles for the middle GEMMs (grid 8x4xB = 128 blocks), with
// global prefetch one k-step ahead (removes ~16x exposed L2 latency).
// ---------------------------------------------------------------------------
struct Smem3264 {
    float As[16][36];
    float Bs[16][68];
};

// NT: C[m][n] = sum_k A[m][k] * B[n][k]
__device__ __forceinline__ void gemm_nt_3264(Smem3264& s,
                                             const float* __restrict__ A,
                                             const float* __restrict__ B,
                                             float* __restrict__ C) {
    const int tid = threadIdx.x;
    const int row = tid >> 2, kq = (tid & 3) * 4;
    const int tx = tid & 15, ty = tid >> 4;
    const int n0 = tx * 4, m0 = ty * 2;
    float acc[2][4] = {};
    float4 a, bv;
    if (tid < 128) a = *(const float4*)(A + (size_t)row * 256 + kq);
    bv = *(const float4*)(B + (size_t)row * 256 + kq);
    for (int kt = 0; kt < 16; kt++) {
        if (tid < 128) {
#pragma unroll
            for (int j = 0; j < 4; j++) s.As[kq + j][row] = ((const float*)&a)[j];
        }
#pragma unroll
        for (int j = 0; j < 4; j++) s.Bs[kq + j][row] = ((const float*)&bv)[j];
        __syncthreads();
        if (kt + 1 < 16) {
            if (tid < 128)
                a = *(const float4*)(A + (size_t)row * 256 + (kt + 1) * 16 + kq);
            bv = *(const float4*)(B + (size_t)row * 256 + (kt + 1) * 16 + kq);
        }
#pragma unroll
        for (int kk = 0; kk < 16; kk++) {
            const float av0 = s.As[kk][m0];
            const float av1 = s.As[kk][m0 + 1];
#pragma unroll
            for (int j = 0; j < 4; j++) {
                const float bb = s.Bs[kk][n0 + j];
                acc[0][j] += av0 * bb;
                acc[1][j] += av1 * bb;
            }
        }
        __syncthreads();
    }
#pragma unroll
    for (int i = 0; i < 2; i++) {
        float4 v;
        v.x = acc[i][0]; v.y = acc[i][1]; v.z = acc[i][2]; v.w = acc[i][3];
        *(float4*)(C + (size_t)(m0 + i) * 256 + n0) = v;
    }
}

// NN: C[m][n] = sum_k A[m][k] * B[k][n]  (B row-major [k][n], ldb=256)
__device__ __forceinline__ void gemm_nn_3264(Smem3264& s,
                                             const float* __restrict__ A,
                                             const float* __restrict__ B,
                                             float* __restrict__ C) {
    const int tid = threadIdx.x;
    const int row = tid >> 2, kq = (tid & 3) * 4;
    const int kr = tid >> 4, cq = (tid & 15) * 4;
    const int tx = tid & 15, ty = tid >> 4;
    const int n0 = tx * 4, m0 = ty * 2;
    float acc[2][4] = {};
    float4 a, bv;
    if (tid < 128) a = *(const float4*)(A + (size_t)row * 256 + kq);
    bv = *(const float4*)(B + (size_t)kr * 256 + cq);
    for (int kt = 0; kt < 16; kt++) {
        if (tid < 128) {
#pragma unroll
            for (int j = 0; j < 4; j++) s.As[kq + j][row] = ((const float*)&a)[j];
        }
#pragma unroll
        for (int j = 0; j < 4; j++) s.Bs[kr][cq + j] = ((const float*)&bv)[j];
        __syncthreads();
        if (kt + 1 < 16) {
            if (tid < 128)
                a = *(const float4*)(A + (size_t)row * 256 + (kt + 1) * 16 + kq);
            bv = *(const float4*)(B + (size_t)((kt + 1) * 16 + kr) * 256 + cq);
        }
#pragma unroll
        for (int kk = 0; kk < 16; kk++) {
            const float av0 = s.As[kk][m0];
            const float av1 = s.As[kk][m0 + 1];
#pragma unroll
            for (int j = 0; j < 4; j++) {
                const float bb = s.Bs[kk][n0 + j];
                acc[0][j] += av0 * bb;
                acc[1][j] += av1 * bb;
            }
        }
        __syncthreads();
    }
#pragma unroll
    for (int i = 0; i < 2; i++) {
        float4 v;
        v.x = acc[i][0]; v.y = acc[i][1]; v.z = acc[i][2]; v.w = acc[i][3];
        *(float4*)(C + (size_t)(m0 + i) * 256 + n0) = v;
    }
}

__global__ void __launch_bounds__(256) gemm_h2_kernel(const float* __restrict__ wk) {
    __shared__ Smem3264 s;
    const int bx = blockIdx.x, by = blockIdx.y, b = blockIdx.z;
    gemm_nt_3264(s, wk + (size_t)bx * 32 * 256,
                 gG + (size_t)b * 65536 + (size_t)by * 64 * 256,
                 gH2 + (size_t)b * 65536 + (size_t)bx * 32 * 256 + by * 64);
}
__global__ void __launch_bounds__(256) gemm_attn_kernel(const float* __restrict__ wq) {
    __shared__ Smem3264 s;
    const int bx = blockIdx.x, by = blockIdx.y, b = blockIdx.z;
    gemm_nt_3264(s, wq + (size_t)bx * 32 * 256,
                 gH2 + (size_t)b * 65536 + (size_t)by * 64 * 256,
                 gAm + (size_t)b * 65536 + (size_t)bx * 32 * 256 + by * 64);
}
// M[q][c] = sum_k A[q][k] * W_V[k][c]  (NN — no transpose of W_V needed)
__global__ void __launch_bounds__(256) gemm_m_kernel(const float* __restrict__ wv) {
    __shared__ Smem3264 s;
    const int bx = blockIdx.x, by = blockIdx.y, b = blockIdx.z;
    gemm_nn_3264(s, gAm + (size_t)b * 65536 + (size_t)bx * 32 * 256,
                 wv + by * 64,
                 gM + (size_t)b * 65536 + (size_t)bx * 32 * 256 + by * 64);
}

// ---------------------------------------------------------------------------
// Softmax over q (axis=-2), grid (16, B): 16 cols/block, 16 q per thread.
// ---------------------------------------------------------------------------
__global__ void __launch_bounds__(256) softmax_kernel() {
    const int b = blockIdx.y;
    const int tc = threadIdx.x & 15, tq = threadIdx.x >> 4;
    const int col = blockIdx.x * 16 + tc;
    float* Ab = gAm + (size_t)b * 65536;

    float v[16];
    float m = -3.0e38f;
#pragma unroll
    for (int qi = 0; qi < 16; qi++) {
        v[qi] = Ab[(size_t)(tq + qi * 16) * 256 + col];
        m = fmaxf(m, v[qi]);
    }
    __shared__ float red[16][16];
    red[tq][tc] = m;
    __syncthreads();
    float mm = red[0][tc];
#pragma unroll
    for (int r = 1; r < 16; r++) mm = fmaxf(mm, red[r][tc]);
    __syncthreads();
    float ssum = 0.f;
#pragma unroll
    for (int qi = 0; qi < 16; qi++) {
        v[qi] = expf(v[qi] - mm);
        ssum += v[qi];
    }
    red[tq][tc] = ssum;
    __syncthreads();
    float tot = 0.f;
#pragma unroll
    for (int r = 0; r < 16; r++) tot += red[r][tc];
    const float inv = 1.f / tot;
#pragma unroll
    for (int qi = 0; qi < 16; qi++)
        Ab[(size_t)(tq + qi * 16) * 256 + col] = v[qi] * inv;
}

// ---------------------------------------------------------------------------
// Phase 5: y[b] = M[b] @ x[b] via mma.sync, 1x TF32, 2-stage double buffer
// (one sync per k-step; STS of next stage overlaps MMA on current stage;
//  globals prefetched one full iteration ahead).
// ---------------------------------------------------------------------------
__global__ void __launch_bounds__(256, 2) final_mma(const float* __restrict__ x,
                                                    float* __restrict__ y) {
    __shared__ float2 Ap[2][128][10];
    __shared__ float Bs[2][16][136];

    const int lx = blockIdx.x, qy = blockIdx.y, b = blockIdx.z;
    const float* Mb = gM + (size_t)b * 65536 + (size_t)qy * 128 * 256;
    const float* xb = x + (size_t)b * CDIM * LDIM + (size_t)lx * 128;
    float* yb = y + ((size_t)b * CDIM + (size_t)qy * 128) * LDIM + (size_t)lx * 128;

    const int tid = threadIdx.x;
    const int warp = tid >> 5, lane = tid & 31;
    const int g = lane >> 2, tg = lane & 3;
    const int m0 = (warp >> 2) * 64, n0 = (warp & 3) * 32;
    const int lrow = tid >> 2, lkq = (tid & 3) * 4;
    const int brow = tid >> 5, blq = (tid & 31) * 4;
    const int aslot0 = (lkq >= 8) ? 4 : 0;
    const int acomp = ((lkq >> 2) & 1);

    float acc[4][4][4];
#pragma unroll
    for (int i = 0; i < 4; i++)
#pragma unroll
        for (int j = 0; j < 4; j++)
#pragma unroll
            for (int k = 0; k < 4; k++) acc[i][j][k] = 0.f;

    const float* A0 = Mb + (size_t)lrow * 256 + lkq;
    const float* A1 = A0 + (size_t)64 * 256;
    const float* B0 = xb + (size_t)brow * LDIM + blq;
    const float* B1 = B0 + (size_t)8 * LDIM;

#define FIN_STORE(st)                                                          \
    do {                                                                       \
        float* a0p = (float*)&Ap[st][lrow][aslot0];                            \
        float* a1p = (float*)&Ap[st][lrow + 64][aslot0];                       \
        _Pragma("unroll") for (int j = 0; j < 4; j++) {                        \
            a0p[2 * j + acomp] = tf32_hi(((const float*)&va0)[j]);             \
            a1p[2 * j + acomp] = tf32_hi(((const float*)&va1)[j]);             \
            Bs[st][brow][blq + j] = tf32_hi(((const float*)&vb0)[j]);          \
            Bs[st][brow + 8][blq + j] = tf32_hi(((const float*)&vb1)[j]);      \
        }                                                                      \
    } while (0)

    // Prologue: load kt=0, store stage 0, prefetch kt=1.
    float4 va0 = *(const float4*)A0;
    float4 va1 = *(const float4*)A1;
    float4 vb0 = *(const float4*)B0;
    float4 vb1 = *(const float4*)B1;
    FIN_STORE(0);
    va0 = *(const float4*)(A0 + 16);
    va1 = *(const float4*)(A1 + 16);
    vb0 = *(const float4*)(B0 + (size_t)16 * LDIM);
    vb1 = *(const float4*)(B1 + (size_t)16 * LDIM);
    __syncthreads();

    for (int kt = 0; kt < 16; kt++) {
        const int p = kt & 1;
        if (kt + 1 < 16) {
            const int pn = p ^ 1;
            FIN_STORE(pn);
            if (kt + 2 < 16) {
                va0 = *(const float4*)(A0 + (kt + 2) * 16);
                va1 = *(const float4*)(A1 + (kt + 2) * 16);
                vb0 = *(const float4*)(B0 + (size_t)(kt + 2) * 16 * LDIM);
                vb1 = *(const float4*)(B1 + (size_t)(kt + 2) * 16 * LDIM);
            }
        }
#pragma unroll
        for (int s = 0; s < 2; s++) {
            const int k0 = s * 8;
            const int sl = s * 4 + tg;
            uint32_t ah[4][4], bh[4][2];
#pragma unroll
            for (int mt = 0; mt < 4; mt++) {
                const int r = m0 + mt * 16 + g;
                float2 p0 = Ap[p][r][sl];
                float2 p1 = Ap[p][r + 8][sl];
                ah[mt][0] = __float_as_uint(p0.x);
                ah[mt][1] = __float_as_uint(p1.x);
                ah[mt][2] = __float_as_uint(p0.y);
                ah[mt][3] = __float_as_uint(p1.y);
            }
#pragma unroll
            for (int nt = 0; nt < 4; nt++) {
                const int cn = n0 + nt * 8 + g;
                bh[nt][0] = __float_as_uint(Bs[p][k0 + tg][cn]);
                bh[nt][1] = __float_as_uint(Bs[p][k0 + tg + 4][cn]);
            }
#pragma unroll
            for (int mt = 0; mt < 4; mt++)
#pragma unroll
                for (int nt = 0; nt < 4; nt++)
                    MMA_TF32(acc[mt][nt], ah[mt], bh[nt]);
        }
        __syncthreads();
    }
#undef FIN_STORE

#pragma unroll
    for (int mt = 0; mt < 4; mt++)
#pragma unroll
        for (int nt = 0; nt < 4; nt++) {
            const int r = m0 + mt * 16 + g;
            const int c = n0 + nt * 8 + 2 * tg;
            float2 v0; v0.x = acc[mt][nt][0]; v0.y = acc[mt][nt][1];
            float2 v1; v1.x = acc[mt][nt][2]; v1.y = acc[mt][nt][3];
            *(float2*)(yb + (size_t)r * LDIM + c) = v0;
            *(float2*)(yb + (size_t)(r + 8) * LDIM + c) = v1;
        }
}

// ---------------------------------------------------------------------------
// Launch
// ---------------------------------------------------------------------------
extern "C" void kernel_launch(void* const* d_in, const int* in_sizes, int n_in,
                              void* d_out, int out_size) {
    const float *x = nullptr, *wq = nullptr, *wk = nullptr, *wv = nullptr;
    for (int i = 0; i < n_in; i++) {
        if (in_sizes[i] == BDIM * CDIM * LDIM) {
            x = (const float*)d_in[i];
        } else if (!wq) wq = (const float*)d_in[i];
        else if (!wk) wk = (const float*)d_in[i];
        else wv = (const float*)d_in[i];
    }
    float* y = (float*)d_out;

    gram_mma<<<dim3(3, NSPLIT, BDIM), 256>>>(x);
    gram_reduce<<<dim3(192, BDIM), 256>>>();
    sym_diag<<<dim3(10, 2, BDIM), 256>>>();
    gemm_h2_kernel<<<dim3(8, 4, BDIM), 256>>>(wk);
    gemm_attn_kernel<<<dim3(8, 4, BDIM), 256>>>(wq);
    softmax_kernel<<<dim3(16, BDIM), 256>>>();
    gemm_m_kernel<<<dim3(8, 4, BDIM), 256>>>(wv);
    final_mma<<<dim3(LDIM / 128, 2, BDIM), 256>>>(x, y);
}